// round 1
// baseline (speedup 1.0000x reference)
#include <cuda_runtime.h>
#include <math.h>

// Problem constants
#define BB 16
#define QQ 64
#define CC 512
#define DD 512
#define D4 2048
#define MTOT (BB*CC)   // 8192

// Scratch (device globals: allocation-free rule)
__device__ float g_cq[BB*CC];          // contexts @ w_c
__device__ float g_qq[BB*QQ];          // questions @ w_q
__device__ float g_m[BB*CC];           // rowmax of sim over q
__device__ float g_attn[BB*CC];        // softmax_c of g_m
__device__ float g_h[BB*DD];           // h_tilde
__device__ float g_u[(size_t)BB*CC*DD];        // u_tilde  (16.8 MB)
__device__ float g_mm[(size_t)MTOT*D4];        // megamerge (64 MB)

// ---------------------------------------------------------------------------
// Kernel 0: cq[b,c] = ctx_row . w_c ; qq[b,q] = q_row . w_q   (warp per row)
// ---------------------------------------------------------------------------
__global__ void k_rowdots(const float* __restrict__ questions,
                          const float* __restrict__ contexts,
                          const float* __restrict__ sim_w) {
    int gw   = (blockIdx.x * blockDim.x + threadIdx.x) >> 5;
    int lane = threadIdx.x & 31;
    const float* row;
    const float* w;
    float* out;
    if (gw < BB*CC) {
        row = contexts + (size_t)gw * DD; w = sim_w;        out = g_cq + gw;
    } else {
        int r = gw - BB*CC;
        if (r >= BB*QQ) return;
        row = questions + (size_t)r * DD; w = sim_w + DD;   out = g_qq + r;
    }
    float s = 0.f;
    #pragma unroll 4
    for (int d = lane; d < DD; d += 32) s += row[d] * w[d];
    #pragma unroll
    for (int o = 16; o > 0; o >>= 1) s += __shfl_xor_sync(0xffffffffu, s, o);
    if (lane == 0) *out = s;
}

// ---------------------------------------------------------------------------
// Kernel 1: per (b, 64-row c-tile):
//   sim tile [64c x 64q] = (ctx*w_p) @ questions^T + cq + qq
//   row-max -> g_m ; row softmax (Q=64 local) ; u = P @ questions -> g_u
// ---------------------------------------------------------------------------
__global__ __launch_bounds__(256) void k_sim_u(
    const float* __restrict__ questions,
    const float* __restrict__ contexts,
    const float* __restrict__ sim_w) {
    __shared__ float sh[4224 + 4352];   // s_sim[64][66] + s_q2[64][68]
    int b  = blockIdx.x >> 3;
    int ct = blockIdx.x & 7;
    int tid = threadIdx.x;
    int tx = tid & 15, ty = tid >> 4;

    const float* wp  = sim_w + 2*DD;
    const float* ctx = contexts + ((size_t)b*CC + ct*64) * DD;
    const float* qs  = questions + (size_t)b*QQ*DD;

    float acc[4][4];
    #pragma unroll
    for (int i = 0; i < 4; i++)
        #pragma unroll
        for (int j = 0; j < 4; j++) acc[i][j] = 0.f;

    float* s_a = sh;            // [32][64]  (k-major)
    float* s_b = sh + 2048;     // [32][64]

    // Phase A: sim tile GEMM, K = 512 in chunks of 32
    for (int k0 = 0; k0 < DD; k0 += 32) {
        #pragma unroll
        for (int i = 0; i < 2; i++) {
            int li  = tid*2 + i;
            int row = li >> 3;      // 0..63
            int kq  = li & 7;       // float4 index within 32
            float4 av = *(const float4*)(ctx + (size_t)row*DD + k0 + kq*4);
            float4 wv = *(const float4*)(wp + k0 + kq*4);
            s_a[(kq*4+0)*64 + row] = av.x * wv.x;
            s_a[(kq*4+1)*64 + row] = av.y * wv.y;
            s_a[(kq*4+2)*64 + row] = av.z * wv.z;
            s_a[(kq*4+3)*64 + row] = av.w * wv.w;
            float4 qv = *(const float4*)(qs + (size_t)row*DD + k0 + kq*4);
            s_b[(kq*4+0)*64 + row] = qv.x;
            s_b[(kq*4+1)*64 + row] = qv.y;
            s_b[(kq*4+2)*64 + row] = qv.z;
            s_b[(kq*4+3)*64 + row] = qv.w;
        }
        __syncthreads();
        #pragma unroll
        for (int k = 0; k < 32; k++) {
            float4 av = *(float4*)&s_a[k*64 + ty*4];
            float4 bv = *(float4*)&s_b[k*64 + tx*4];
            float a4[4] = {av.x, av.y, av.z, av.w};
            float b4[4] = {bv.x, bv.y, bv.z, bv.w};
            #pragma unroll
            for (int i = 0; i < 4; i++)
                #pragma unroll
                for (int j = 0; j < 4; j++) acc[i][j] += a4[i] * b4[j];
        }
        __syncthreads();
    }

    // Phase B: add cq/qq, write sim to smem, softmax per row, rowmax -> g_m
    float* s_sim = sh;                  // [64][66]
    #pragma unroll
    for (int i = 0; i < 4; i++) {
        float cqv = g_cq[b*CC + ct*64 + ty*4 + i];
        #pragma unroll
        for (int j = 0; j < 4; j++) {
            float qqv = g_qq[b*QQ + tx*4 + j];
            s_sim[(ty*4+i)*66 + tx*4 + j] = acc[i][j] + cqv + qqv;
        }
    }
    __syncthreads();

    int wid = tid >> 5, lane = tid & 31;
    #pragma unroll
    for (int rr = 0; rr < 8; rr++) {
        int r = wid*8 + rr;
        float v0 = s_sim[r*66 + lane];
        float v1 = s_sim[r*66 + 32 + lane];
        float mx = fmaxf(v0, v1);
        #pragma unroll
        for (int o = 16; o > 0; o >>= 1) mx = fmaxf(mx, __shfl_xor_sync(0xffffffffu, mx, o));
        float e0 = __expf(v0 - mx), e1 = __expf(v1 - mx);
        float sm = e0 + e1;
        #pragma unroll
        for (int o = 16; o > 0; o >>= 1) sm += __shfl_xor_sync(0xffffffffu, sm, o);
        float inv = 1.f / sm;
        s_sim[r*66 + lane]      = e0 * inv;
        s_sim[r*66 + 32 + lane] = e1 * inv;
        if (lane == 0) g_m[b*CC + ct*64 + r] = mx;
    }
    __syncthreads();

    // Phase C: u[64 x 512] = P[64x64] @ qs[64x512], 64-wide d chunks
    float* s_q2 = sh + 4224;    // [64][68]
    for (int d0 = 0; d0 < DD; d0 += 64) {
        #pragma unroll
        for (int i = 0; i < 4; i++) {
            int li  = tid + i*256;
            int row = li >> 4;      // q 0..63
            int dq  = li & 15;      // float4 within 64
            float4 qv = *(const float4*)(qs + (size_t)row*DD + d0 + dq*4);
            *(float4*)&s_q2[row*68 + dq*4] = qv;
        }
        __syncthreads();
        float a2[4][4];
        #pragma unroll
        for (int i = 0; i < 4; i++)
            #pragma unroll
            for (int j = 0; j < 4; j++) a2[i][j] = 0.f;
        #pragma unroll 8
        for (int k = 0; k < 64; k++) {
            float p0 = s_sim[(ty*4+0)*66 + k];
            float p1 = s_sim[(ty*4+1)*66 + k];
            float p2 = s_sim[(ty*4+2)*66 + k];
            float p3 = s_sim[(ty*4+3)*66 + k];
            float4 qv = *(float4*)&s_q2[k*68 + tx*4];
            float q4[4] = {qv.x, qv.y, qv.z, qv.w};
            #pragma unroll
            for (int j = 0; j < 4; j++) {
                a2[0][j] += p0 * q4[j];
                a2[1][j] += p1 * q4[j];
                a2[2][j] += p2 * q4[j];
                a2[3][j] += p3 * q4[j];
            }
        }
        #pragma unroll
        for (int i = 0; i < 4; i++) {
            float4 w4 = make_float4(a2[i][0], a2[i][1], a2[i][2], a2[i][3]);
            *(float4*)&g_u[((size_t)b*CC + ct*64 + ty*4 + i)*DD + d0 + tx*4] = w4;
        }
        __syncthreads();
    }
}

// ---------------------------------------------------------------------------
// Kernel 2a: attn[b,:] = softmax over C of g_m[b,:]   (block per batch)
// ---------------------------------------------------------------------------
__global__ void k_attn() {
    __shared__ float red[256];
    int b = blockIdx.x, tid = threadIdx.x;
    float v0 = g_m[b*CC + tid], v1 = g_m[b*CC + 256 + tid];
    float mx = fmaxf(v0, v1);
    red[tid] = mx; __syncthreads();
    for (int s = 128; s > 0; s >>= 1) {
        if (tid < s) red[tid] = fmaxf(red[tid], red[tid + s]);
        __syncthreads();
    }
    mx = red[0]; __syncthreads();
    float e0 = __expf(v0 - mx), e1 = __expf(v1 - mx);
    red[tid] = e0 + e1; __syncthreads();
    for (int s = 128; s > 0; s >>= 1) {
        if (tid < s) red[tid] += red[tid + s];
        __syncthreads();
    }
    float inv = 1.f / red[0];
    g_attn[b*CC + tid]       = e0 * inv;
    g_attn[b*CC + 256 + tid] = e1 * inv;
}

// ---------------------------------------------------------------------------
// Kernel 2b: h[b,d] = sum_c attn[b,c] * ctx[b,c,d]
// grid = B * 4 blocks (128 d per block), 128 threads
// ---------------------------------------------------------------------------
__global__ void k_h(const float* __restrict__ contexts) {
    __shared__ float sa[CC];
    int b = blockIdx.x >> 2;
    int d = (blockIdx.x & 3) * 128 + threadIdx.x;
    for (int i = threadIdx.x; i < CC; i += 128) sa[i] = g_attn[b*CC + i];
    __syncthreads();
    const float* ctx = contexts + (size_t)b*CC*DD;
    float acc = 0.f;
    #pragma unroll 8
    for (int c = 0; c < CC; c++) acc += sa[c] * ctx[(size_t)c*DD + d];
    g_h[b*DD + d] = acc;
}

// ---------------------------------------------------------------------------
// Kernel 3: materialize megamerge [M=8192, K=2048] (float4 grid-stride)
// ---------------------------------------------------------------------------
__global__ void k_mm(const float* __restrict__ contexts) {
    size_t i4 = (size_t)blockIdx.x * 256 + threadIdx.x;  // over MTOT*D4/4 = 4194304
    int m   = (int)(i4 >> 9);        // row 0..8191
    int k4  = (int)(i4 & 511);       // float4 within 2048
    int seg = k4 >> 7;
    int off = (k4 & 127) * 4;
    int b   = m >> 9;
    float4 cv = *(const float4*)(contexts + (size_t)m*DD + off);
    float4 r;
    if (seg == 0) {
        r = cv;
    } else if (seg == 3) {
        float4 hv = *(const float4*)(g_h + (size_t)b*DD + off);
        r = make_float4(cv.x*hv.x, cv.y*hv.y, cv.z*hv.z, cv.w*hv.w);
    } else {
        float4 uv = *(const float4*)(g_u + (size_t)m*DD + off);
        r = (seg == 1) ? uv
                       : make_float4(uv.x*cv.x, uv.y*cv.y, uv.z*cv.z, uv.w*cv.w);
    }
    ((float4*)g_mm)[i4] = r;
}

// ---------------------------------------------------------------------------
// Kernel 4: SGEMM  out[M=8192, N=2048] = g_mm @ qac_w^T + qac_b
// Both operands K-major. 128x128 tile, BK=16, 8x8 per thread, reg prefetch.
// ---------------------------------------------------------------------------
#define BM 128
#define BN 128
#define BK 16
__global__ __launch_bounds__(256) void k_gemm(
    const float* __restrict__ Wt,     // [2048][2048] K-major
    const float* __restrict__ bias,   // [2048]
    float* __restrict__ out) {
    __shared__ float As[BK][BM];
    __shared__ float Bs[BK][BN];
    int bx = blockIdx.x;   // N tile 0..15
    int by = blockIdx.y;   // M tile 0..63
    int tid = threadIdx.x;
    int tx = tid & 15, ty = tid >> 4;

    const float* A  = g_mm + (size_t)(by*BM)*D4;
    const float* Bp = Wt   + (size_t)(bx*BN)*D4;

    float acc[8][8];
    #pragma unroll
    for (int i = 0; i < 8; i++)
        #pragma unroll
        for (int j = 0; j < 8; j++) acc[i][j] = 0.f;

    // loader mapping: li = tid*2+i -> row = li>>2 (0..127), kq = li&3
    int lrow0 = (tid*2 + 0) >> 2, lkq0 = (tid*2 + 0) & 3;
    int lrow1 = (tid*2 + 1) >> 2, lkq1 = (tid*2 + 1) & 3;

    float4 ra0, ra1, rb0, rb1;
    // prologue: load k0 = 0
    ra0 = *(const float4*)(A  + (size_t)lrow0*D4 + lkq0*4);
    ra1 = *(const float4*)(A  + (size_t)lrow1*D4 + lkq1*4);
    rb0 = *(const float4*)(Bp + (size_t)lrow0*D4 + lkq0*4);
    rb1 = *(const float4*)(Bp + (size_t)lrow1*D4 + lkq1*4);

    for (int k0 = 0; k0 < D4; k0 += BK) {
        // store current regs -> smem
        As[lkq0*4+0][lrow0] = ra0.x; As[lkq0*4+1][lrow0] = ra0.y;
        As[lkq0*4+2][lrow0] = ra0.z; As[lkq0*4+3][lrow0] = ra0.w;
        As[lkq1*4+0][lrow1] = ra1.x; As[lkq1*4+1][lrow1] = ra1.y;
        As[lkq1*4+2][lrow1] = ra1.z; As[lkq1*4+3][lrow1] = ra1.w;
        Bs[lkq0*4+0][lrow0] = rb0.x; Bs[lkq0*4+1][lrow0] = rb0.y;
        Bs[lkq0*4+2][lrow0] = rb0.z; Bs[lkq0*4+3][lrow0] = rb0.w;
        Bs[lkq1*4+0][lrow1] = rb1.x; Bs[lkq1*4+1][lrow1] = rb1.y;
        Bs[lkq1*4+2][lrow1] = rb1.z; Bs[lkq1*4+3][lrow1] = rb1.w;
        __syncthreads();

        int kn = k0 + BK;
        if (kn < D4) {  // prefetch next tile into regs
            ra0 = *(const float4*)(A  + (size_t)lrow0*D4 + kn + lkq0*4);
            ra1 = *(const float4*)(A  + (size_t)lrow1*D4 + kn + lkq1*4);
            rb0 = *(const float4*)(Bp + (size_t)lrow0*D4 + kn + lkq0*4);
            rb1 = *(const float4*)(Bp + (size_t)lrow1*D4 + kn + lkq1*4);
        }

        #pragma unroll
        for (int k = 0; k < BK; k++) {
            float4 a0 = *(float4*)&As[k][ty*8];
            float4 a1 = *(float4*)&As[k][ty*8 + 4];
            float4 b0 = *(float4*)&Bs[k][tx*8];
            float4 b1 = *(float4*)&Bs[k][tx*8 + 4];
            float am[8] = {a0.x,a0.y,a0.z,a0.w,a1.x,a1.y,a1.z,a1.w};
            float bn[8] = {b0.x,b0.y,b0.z,b0.w,b1.x,b1.y,b1.z,b1.w};
            #pragma unroll
            for (int i = 0; i < 8; i++)
                #pragma unroll
                for (int j = 0; j < 8; j++) acc[i][j] += am[i] * bn[j];
        }
        __syncthreads();
    }

    // epilogue with bias
    int m0 = by*BM + ty*8;
    int n0 = bx*BN + tx*8;
    float bj[8];
    #pragma unroll
    for (int j = 0; j < 8; j++) bj[j] = bias[n0 + j];
    #pragma unroll
    for (int i = 0; i < 8; i++) {
        float* o = out + (size_t)(m0 + i)*D4 + n0;
        float4 w0 = make_float4(acc[i][0]+bj[0], acc[i][1]+bj[1], acc[i][2]+bj[2], acc[i][3]+bj[3]);
        float4 w1 = make_float4(acc[i][4]+bj[4], acc[i][5]+bj[5], acc[i][6]+bj[6], acc[i][7]+bj[7]);
        *(float4*)(o)     = w0;
        *(float4*)(o + 4) = w1;
    }
}

// ---------------------------------------------------------------------------
extern "C" void kernel_launch(void* const* d_in, const int* in_sizes, int n_in,
                              void* d_out, int out_size) {
    const float* questions = (const float*)d_in[0];
    const float* contexts  = (const float*)d_in[1];
    const float* sim_w     = (const float*)d_in[2];
    const float* qac_w     = (const float*)d_in[3];
    const float* qac_b     = (const float*)d_in[4];
    float* out = (float*)d_out;

    k_rowdots<<<1152, 256>>>(questions, contexts, sim_w);
    k_sim_u<<<128, 256>>>(questions, contexts, sim_w);
    k_attn<<<16, 256>>>();
    k_h<<<64, 128>>>(contexts);
    k_mm<<<16384, 256>>>(contexts);
    k_gemm<<<dim3(16, 64), 256>>>(qac_w, qac_b, out);
}

// round 3
// speedup vs baseline: 2.3898x; 2.3898x over previous
#include <cuda_runtime.h>
#include <cuda_bf16.h>
#include <math.h>
#include <stdint.h>

// Problem constants
#define BB 16
#define QQ 64
#define CC 512
#define DD 512
#define D4 2048
#define MTOT (BB*CC)   // 8192

// Scratch (device globals: allocation-free rule)
__device__ float g_cq[BB*CC];
__device__ float g_qq[BB*QQ];
__device__ float g_m[BB*CC];
__device__ float g_attn[BB*CC];
__device__ float g_h[BB*DD];
__device__ float g_u[(size_t)BB*CC*DD];                         // 16.8 MB
__device__ __align__(16) __nv_bfloat16 g_Ahi[(size_t)MTOT*D4];  // 32 MB
__device__ __align__(16) __nv_bfloat16 g_Alo[(size_t)MTOT*D4];  // 32 MB
__device__ __align__(16) __nv_bfloat16 g_Bhi[(size_t)D4*D4];    // 8 MB
__device__ __align__(16) __nv_bfloat16 g_Blo[(size_t)D4*D4];    // 8 MB

__device__ __forceinline__ uint32_t smem_u32(const void* p) {
    uint32_t a;
    asm("{ .reg .u64 t; cvta.to.shared.u64 t, %1; cvt.u32.u64 %0, t; }"
        : "=r"(a) : "l"(p));
    return a;
}

#define LDSM4(r, addr) \
    asm volatile("ldmatrix.sync.aligned.m8n8.x4.shared.b16 {%0,%1,%2,%3}, [%4];" \
        : "=r"((r)[0]), "=r"((r)[1]), "=r"((r)[2]), "=r"((r)[3]) : "r"(addr))

#define CP16(dst, src) \
    asm volatile("cp.async.cg.shared.global [%0], [%1], 16;" \
        :: "r"(dst), "l"(src) : "memory")

__device__ __forceinline__ void mma16816(float* d, const uint32_t* a,
                                         uint32_t b0, uint32_t b1) {
    asm volatile(
        "mma.sync.aligned.m16n8k16.row.col.f32.bf16.bf16.f32 "
        "{%0,%1,%2,%3}, {%4,%5,%6,%7}, {%8,%9}, {%0,%1,%2,%3};"
        : "+f"(d[0]), "+f"(d[1]), "+f"(d[2]), "+f"(d[3])
        : "r"(a[0]), "r"(a[1]), "r"(a[2]), "r"(a[3]), "r"(b0), "r"(b1));
}

// bf16 two-term split helper: packs (x,y) hi and lo pairs
__device__ __forceinline__ void split2(float x, float y, uint32_t& hi, uint32_t& lo) {
    __nv_bfloat16 hx = __float2bfloat16(x);
    __nv_bfloat16 hy = __float2bfloat16(y);
    __nv_bfloat16 lx = __float2bfloat16(x - __bfloat162float(hx));
    __nv_bfloat16 ly = __float2bfloat16(y - __bfloat162float(hy));
    hi = ((uint32_t)__bfloat16_as_ushort(hy) << 16) | (uint32_t)__bfloat16_as_ushort(hx);
    lo = ((uint32_t)__bfloat16_as_ushort(ly) << 16) | (uint32_t)__bfloat16_as_ushort(lx);
}

// ---------------------------------------------------------------------------
// Kernel 0: cq[b,c] = ctx_row . w_c ; qq[b,q] = q_row . w_q   (warp per row)
// ---------------------------------------------------------------------------
__global__ void k_rowdots(const float* __restrict__ questions,
                          const float* __restrict__ contexts,
                          const float* __restrict__ sim_w) {
    int gw   = (blockIdx.x * blockDim.x + threadIdx.x) >> 5;
    int lane = threadIdx.x & 31;
    const float* row;
    const float* w;
    float* out;
    if (gw < BB*CC) {
        row = contexts + (size_t)gw * DD; w = sim_w;        out = g_cq + gw;
    } else {
        int r = gw - BB*CC;
        if (r >= BB*QQ) return;
        row = questions + (size_t)r * DD; w = sim_w + DD;   out = g_qq + r;
    }
    float s = 0.f;
    #pragma unroll 4
    for (int d = lane; d < DD; d += 32) s += row[d] * w[d];
    #pragma unroll
    for (int o = 16; o > 0; o >>= 1) s += __shfl_xor_sync(0xffffffffu, s, o);
    if (lane == 0) *out = s;
}

// ---------------------------------------------------------------------------
// Kernel 1: sim tile + softmax + u_tilde
// ---------------------------------------------------------------------------
__global__ __launch_bounds__(256) void k_sim_u(
    const float* __restrict__ questions,
    const float* __restrict__ contexts,
    const float* __restrict__ sim_w) {
    __shared__ float sh[4224 + 4352];
    int b  = blockIdx.x >> 3;
    int ct = blockIdx.x & 7;
    int tid = threadIdx.x;
    int tx = tid & 15, ty = tid >> 4;

    const float* wp  = sim_w + 2*DD;
    const float* ctx = contexts + ((size_t)b*CC + ct*64) * DD;
    const float* qs  = questions + (size_t)b*QQ*DD;

    float acc[4][4];
    #pragma unroll
    for (int i = 0; i < 4; i++)
        #pragma unroll
        for (int j = 0; j < 4; j++) acc[i][j] = 0.f;

    float* s_a = sh;
    float* s_b = sh + 2048;

    for (int k0 = 0; k0 < DD; k0 += 32) {
        #pragma unroll
        for (int i = 0; i < 2; i++) {
            int li  = tid*2 + i;
            int row = li >> 3;
            int kq  = li & 7;
            float4 av = *(const float4*)(ctx + (size_t)row*DD + k0 + kq*4);
            float4 wv = *(const float4*)(wp + k0 + kq*4);
            s_a[(kq*4+0)*64 + row] = av.x * wv.x;
            s_a[(kq*4+1)*64 + row] = av.y * wv.y;
            s_a[(kq*4+2)*64 + row] = av.z * wv.z;
            s_a[(kq*4+3)*64 + row] = av.w * wv.w;
            float4 qv = *(const float4*)(qs + (size_t)row*DD + k0 + kq*4);
            s_b[(kq*4+0)*64 + row] = qv.x;
            s_b[(kq*4+1)*64 + row] = qv.y;
            s_b[(kq*4+2)*64 + row] = qv.z;
            s_b[(kq*4+3)*64 + row] = qv.w;
        }
        __syncthreads();
        #pragma unroll
        for (int k = 0; k < 32; k++) {
            float4 av = *(float4*)&s_a[k*64 + ty*4];
            float4 bv = *(float4*)&s_b[k*64 + tx*4];
            float a4[4] = {av.x, av.y, av.z, av.w};
            float b4[4] = {bv.x, bv.y, bv.z, bv.w};
            #pragma unroll
            for (int i = 0; i < 4; i++)
                #pragma unroll
                for (int j = 0; j < 4; j++) acc[i][j] += a4[i] * b4[j];
        }
        __syncthreads();
    }

    float* s_sim = sh;
    #pragma unroll
    for (int i = 0; i < 4; i++) {
        float cqv = g_cq[b*CC + ct*64 + ty*4 + i];
        #pragma unroll
        for (int j = 0; j < 4; j++) {
            float qqv = g_qq[b*QQ + tx*4 + j];
            s_sim[(ty*4+i)*66 + tx*4 + j] = acc[i][j] + cqv + qqv;
        }
    }
    __syncthreads();

    int wid = tid >> 5, lane = tid & 31;
    #pragma unroll
    for (int rr = 0; rr < 8; rr++) {
        int r = wid*8 + rr;
        float v0 = s_sim[r*66 + lane];
        float v1 = s_sim[r*66 + 32 + lane];
        float mx = fmaxf(v0, v1);
        #pragma unroll
        for (int o = 16; o > 0; o >>= 1) mx = fmaxf(mx, __shfl_xor_sync(0xffffffffu, mx, o));
        float e0 = __expf(v0 - mx), e1 = __expf(v1 - mx);
        float sm = e0 + e1;
        #pragma unroll
        for (int o = 16; o > 0; o >>= 1) sm += __shfl_xor_sync(0xffffffffu, sm, o);
        float inv = 1.f / sm;
        s_sim[r*66 + lane]      = e0 * inv;
        s_sim[r*66 + 32 + lane] = e1 * inv;
        if (lane == 0) g_m[b*CC + ct*64 + r] = mx;
    }
    __syncthreads();

    float* s_q2 = sh + 4224;
    for (int d0 = 0; d0 < DD; d0 += 64) {
        #pragma unroll
        for (int i = 0; i < 4; i++) {
            int li  = tid + i*256;
            int row = li >> 4;
            int dq  = li & 15;
            float4 qv = *(const float4*)(qs + (size_t)row*DD + d0 + dq*4);
            *(float4*)&s_q2[row*68 + dq*4] = qv;
        }
        __syncthreads();
        float a2[4][4];
        #pragma unroll
        for (int i = 0; i < 4; i++)
            #pragma unroll
            for (int j = 0; j < 4; j++) a2[i][j] = 0.f;
        #pragma unroll 8
        for (int k = 0; k < 64; k++) {
            float p0 = s_sim[(ty*4+0)*66 + k];
            float p1 = s_sim[(ty*4+1)*66 + k];
            float p2 = s_sim[(ty*4+2)*66 + k];
            float p3 = s_sim[(ty*4+3)*66 + k];
            float4 qv = *(float4*)&s_q2[k*68 + tx*4];
            float q4[4] = {qv.x, qv.y, qv.z, qv.w};
            #pragma unroll
            for (int j = 0; j < 4; j++) {
                a2[0][j] += p0 * q4[j];
                a2[1][j] += p1 * q4[j];
                a2[2][j] += p2 * q4[j];
                a2[3][j] += p3 * q4[j];
            }
        }
        #pragma unroll
        for (int i = 0; i < 4; i++) {
            float4 w4 = make_float4(a2[i][0], a2[i][1], a2[i][2], a2[i][3]);
            *(float4*)&g_u[((size_t)b*CC + ct*64 + ty*4 + i)*DD + d0 + tx*4] = w4;
        }
        __syncthreads();
    }
}

// ---------------------------------------------------------------------------
// Kernel 2a: attn softmax over C
// ---------------------------------------------------------------------------
__global__ void k_attn() {
    __shared__ float red[256];
    int b = blockIdx.x, tid = threadIdx.x;
    float v0 = g_m[b*CC + tid], v1 = g_m[b*CC + 256 + tid];
    float mx = fmaxf(v0, v1);
    red[tid] = mx; __syncthreads();
    for (int s = 128; s > 0; s >>= 1) {
        if (tid < s) red[tid] = fmaxf(red[tid], red[tid + s]);
        __syncthreads();
    }
    mx = red[0]; __syncthreads();
    float e0 = __expf(v0 - mx), e1 = __expf(v1 - mx);
    red[tid] = e0 + e1; __syncthreads();
    for (int s = 128; s > 0; s >>= 1) {
        if (tid < s) red[tid] += red[tid + s];
        __syncthreads();
    }
    float inv = 1.f / red[0];
    g_attn[b*CC + tid]       = e0 * inv;
    g_attn[b*CC + 256 + tid] = e1 * inv;
}

// ---------------------------------------------------------------------------
// Kernel 2b: h_tilde
// ---------------------------------------------------------------------------
__global__ void k_h(const float* __restrict__ contexts) {
    __shared__ float sa[CC];
    int b = blockIdx.x >> 2;
    int d = (blockIdx.x & 3) * 128 + threadIdx.x;
    for (int i = threadIdx.x; i < CC; i += 128) sa[i] = g_attn[b*CC + i];
    __syncthreads();
    const float* ctx = contexts + (size_t)b*CC*DD;
    float acc = 0.f;
    #pragma unroll 8
    for (int c = 0; c < CC; c++) acc += sa[c] * ctx[(size_t)c*DD + d];
    g_h[b*DD + d] = acc;
}

// ---------------------------------------------------------------------------
// Kernel 3: megamerge -> bf16 hi/lo split (A operand of the big GEMM)
// ---------------------------------------------------------------------------
__global__ void k_mm(const float* __restrict__ contexts) {
    size_t i4 = (size_t)blockIdx.x * 256 + threadIdx.x;   // MTOT*D4/4
    int m   = (int)(i4 >> 9);
    int k4  = (int)(i4 & 511);
    int seg = k4 >> 7;
    int off = (k4 & 127) * 4;
    int b   = m >> 9;
    float4 cv = *(const float4*)(contexts + (size_t)m*DD + off);
    float4 r;
    if (seg == 0) {
        r = cv;
    } else if (seg == 3) {
        float4 hv = *(const float4*)(g_h + (size_t)b*DD + off);
        r = make_float4(cv.x*hv.x, cv.y*hv.y, cv.z*hv.z, cv.w*hv.w);
    } else {
        float4 uv = *(const float4*)(g_u + (size_t)m*DD + off);
        r = (seg == 1) ? uv
                       : make_float4(uv.x*cv.x, uv.y*cv.y, uv.z*cv.z, uv.w*cv.w);
    }
    uint2 h4, l4;
    split2(r.x, r.y, h4.x, l4.x);
    split2(r.z, r.w, h4.y, l4.y);
    ((uint2*)g_Ahi)[i4] = h4;
    ((uint2*)g_Alo)[i4] = l4;
}

// ---------------------------------------------------------------------------
// Kernel 3b: qac_w -> bf16 hi/lo split (B operand)
// ---------------------------------------------------------------------------
__global__ void k_wsplit(const float* __restrict__ w) {
    size_t i4 = (size_t)blockIdx.x * 256 + threadIdx.x;   // D4*D4/4
    float4 v = ((const float4*)w)[i4];
    uint2 h4, l4;
    split2(v.x, v.y, h4.x, l4.x);
    split2(v.z, v.w, h4.y, l4.y);
    ((uint2*)g_Bhi)[i4] = h4;
    ((uint2*)g_Blo)[i4] = l4;
}

// ---------------------------------------------------------------------------
// Kernel 4: mma.sync bf16 GEMM (3-term split, K_eff = 6144)
//   out[8192, 2048] = Ahi*Bhi^T + Alo*Bhi^T + Ahi*Blo^T + bias
// CTA tile 128x128, BK=64 bf16, 2-stage cp.async pipeline.
// 8 warps = 2(M) x 4(N); warp tile 64x32; mma.m16n8k16.
// SMEM rows padded: 64 bf16 data + 8 pad = 144 B row stride.
// ---------------------------------------------------------------------------
#define ROWB 144
#define ASTG (128*ROWB)          // 18432 B
#define STGB (2*ASTG)            // 36864 B (A then B)
#define GSMEM2 (2*STGB)          // 73728 B

__global__ __launch_bounds__(256) void k_gemm_mma(
    const float* __restrict__ bias, float* __restrict__ out) {
    extern __shared__ char smem[];
    uint32_t su = smem_u32(smem);
    int tid  = threadIdx.x;
    int lane = tid & 31;
    int w    = tid >> 5;
    int wm   = w >> 2;          // 0..1
    int wn   = w & 3;           // 0..3
    int n0 = blockIdx.x * 128;
    int m0 = blockIdx.y * 128;

    float acc[4][4][4];
    #pragma unroll
    for (int i = 0; i < 4; i++)
        #pragma unroll
        for (int p = 0; p < 4; p++)
            #pragma unroll
            for (int e = 0; e < 4; e++) acc[i][p][e] = 0.f;

    int lrow = tid >> 3;        // 0..31 row-block stepping by 32? no: u below
    int lchk = tid & 7;         // 16B chunk within 128B row

    // stage loader: 96 outer iters; seg = it>>5 selects operand pair
    auto load_stage = [&](int it, int s) {
        int seg   = it >> 5;
        int kbase = (it & 31) * 64;
        const __nv_bfloat16* Ag = (seg == 1) ? g_Alo : g_Ahi;
        const __nv_bfloat16* Bg = (seg == 2) ? g_Blo : g_Bhi;
        uint32_t sA = su + s*STGB;
        #pragma unroll
        for (int i = 0; i < 4; i++) {
            int row = lrow + i*32;
            const void* ga = Ag + (size_t)(m0 + row)*D4 + kbase + lchk*8;
            const void* gb = Bg + (size_t)(n0 + row)*D4 + kbase + lchk*8;
            uint32_t d = sA + row*ROWB + lchk*16;
            CP16(d, ga);
            CP16(d + ASTG, gb);
        }
        asm volatile("cp.async.commit_group;" ::: "memory");
    };

    load_stage(0, 0);

    // ldmatrix lane addressing (within a 16x16 tile)
    int lr16 = (lane & 7) + ((lane >> 3) & 1) * 8;   // row 0..15
    int lc16 = lane >> 4;                             // chunk 0/1

    for (int it = 0; it < 96; it++) {
        int s = it & 1;
        if (it + 1 < 96) {
            load_stage(it + 1, (it + 1) & 1);
            asm volatile("cp.async.wait_group %0;" :: "n"(1) : "memory");
        } else {
            asm volatile("cp.async.wait_group %0;" :: "n"(0) : "memory");
        }
        __syncthreads();

        uint32_t aW = su + s*STGB + (wm*64 + lr16)*ROWB + lc16*16;
        uint32_t bW = su + s*STGB + ASTG + (wn*32 + lr16)*ROWB + lc16*16;

        #pragma unroll
        for (int j = 0; j < 4; j++) {
            uint32_t af[4][4];
            #pragma unroll
            for (int i = 0; i < 4; i++)
                LDSM4(af[i], aW + i*16*ROWB + j*32);
            uint32_t bf[2][4];
            #pragma unroll
            for (int h = 0; h < 2; h++)
                LDSM4(bf[h], bW + h*16*ROWB + j*32);
            #pragma unroll
            for (int i = 0; i < 4; i++)
                #pragma unroll
                for (int p = 0; p < 4; p++)
                    mma16816(acc[i][p], af[i], bf[p>>1][p&1], bf[p>>1][(p&1)+2]);
        }
        __syncthreads();
    }

    // Epilogue: c0,c1 -> (row g, col 2t,2t+1); c2,c3 -> row g+8
    int g = lane >> 2, t = lane & 3;
    #pragma unroll
    for (int i = 0; i < 4; i++) {
        int row = m0 + wm*64 + i*16 + g;
        #pragma unroll
        for (int p = 0; p < 4; p++) {
            int col = n0 + wn*32 + p*8 + 2*t;
            float b0 = bias[col], b1 = bias[col + 1];
            float2 v0 = make_float2(acc[i][p][0] + b0, acc[i][p][1] + b1);
            float2 v1 = make_float2(acc[i][p][2] + b0, acc[i][p][3] + b1);
            *(float2*)(out + (size_t)row*D4 + col)       = v0;
            *(float2*)(out + (size_t)(row + 8)*D4 + col) = v1;
        }
    }
}

// ---------------------------------------------------------------------------
extern "C" void kernel_launch(void* const* d_in, const int* in_sizes, int n_in,
                              void* d_out, int out_size) {
    const float* questions = (const float*)d_in[0];
    const float* contexts  = (const float*)d_in[1];
    const float* sim_w     = (const float*)d_in[2];
    const float* qac_w     = (const float*)d_in[3];
    const float* qac_b     = (const float*)d_in[4];
    float* out = (float*)d_out;

    cudaFuncSetAttribute(k_gemm_mma, cudaFuncAttributeMaxDynamicSharedMemorySize, GSMEM2);

    k_wsplit<<<4096, 256>>>(qac_w);
    k_rowdots<<<1152, 256>>>(questions, contexts, sim_w);
    k_sim_u<<<128, 256>>>(questions, contexts, sim_w);
    k_attn<<<16, 256>>>();
    k_h<<<64, 128>>>(contexts);
    k_mm<<<16384, 256>>>(contexts);
    k_gemm_mma<<<dim3(16, 64), 256, GSMEM2>>>(qac_b, out);
}

// round 4
// speedup vs baseline: 2.5111x; 1.0508x over previous
#include <cuda_runtime.h>
#include <cuda_bf16.h>
#include <math.h>
#include <stdint.h>

// Problem constants
#define BB 16
#define QQ 64
#define CC 512
#define DD 512
#define D4 2048
#define MTOT (BB*CC)   // 8192

// Scratch (device globals: allocation-free rule)
__device__ float g_cq[BB*CC];
__device__ float g_qq[BB*QQ];
__device__ float g_m[BB*CC];
__device__ float g_attn[BB*CC];
__device__ float g_h[BB*DD];
__device__ float g_u[(size_t)BB*CC*DD];                         // 16.8 MB
__device__ __align__(16) __nv_bfloat16 g_Ahi[(size_t)MTOT*D4];  // 32 MB
__device__ __align__(16) __nv_bfloat16 g_Alo[(size_t)MTOT*D4];  // 32 MB
__device__ __align__(16) __nv_bfloat16 g_Bhi[(size_t)D4*D4];    // 8 MB
__device__ __align__(16) __nv_bfloat16 g_Blo[(size_t)D4*D4];    // 8 MB

__device__ __forceinline__ uint32_t smem_u32(const void* p) {
    uint32_t a;
    asm("{ .reg .u64 t; cvta.to.shared.u64 t, %1; cvt.u32.u64 %0, t; }"
        : "=r"(a) : "l"(p));
    return a;
}

#define LDSM4(r, addr) \
    asm volatile("ldmatrix.sync.aligned.m8n8.x4.shared.b16 {%0,%1,%2,%3}, [%4];" \
        : "=r"((r)[0]), "=r"((r)[1]), "=r"((r)[2]), "=r"((r)[3]) : "r"(addr))

#define CP16(dst, src) \
    asm volatile("cp.async.cg.shared.global [%0], [%1], 16;" \
        :: "r"(dst), "l"(src) : "memory")

__device__ __forceinline__ void mma16816(float* d, const uint32_t* a,
                                         uint32_t b0, uint32_t b1) {
    asm volatile(
        "mma.sync.aligned.m16n8k16.row.col.f32.bf16.bf16.f32 "
        "{%0,%1,%2,%3}, {%4,%5,%6,%7}, {%8,%9}, {%0,%1,%2,%3};"
        : "+f"(d[0]), "+f"(d[1]), "+f"(d[2]), "+f"(d[3])
        : "r"(a[0]), "r"(a[1]), "r"(a[2]), "r"(a[3]), "r"(b0), "r"(b1));
}

// bf16 two-term split helper: packs (x,y) hi and lo pairs
__device__ __forceinline__ void split2(float x, float y, uint32_t& hi, uint32_t& lo) {
    __nv_bfloat16 hx = __float2bfloat16(x);
    __nv_bfloat16 hy = __float2bfloat16(y);
    __nv_bfloat16 lx = __float2bfloat16(x - __bfloat162float(hx));
    __nv_bfloat16 ly = __float2bfloat16(y - __bfloat162float(hy));
    hi = ((uint32_t)__bfloat16_as_ushort(hy) << 16) | (uint32_t)__bfloat16_as_ushort(hx);
    lo = ((uint32_t)__bfloat16_as_ushort(ly) << 16) | (uint32_t)__bfloat16_as_ushort(lx);
}

// ---------------------------------------------------------------------------
// Kernel 0: cq[b,c] = ctx_row . w_c ; qq[b,q] = q_row . w_q   (warp per row)
// ---------------------------------------------------------------------------
__global__ void k_rowdots(const float* __restrict__ questions,
                          const float* __restrict__ contexts,
                          const float* __restrict__ sim_w) {
    int gw   = (blockIdx.x * blockDim.x + threadIdx.x) >> 5;
    int lane = threadIdx.x & 31;
    const float* row;
    const float* w;
    float* out;
    if (gw < BB*CC) {
        row = contexts + (size_t)gw * DD; w = sim_w;        out = g_cq + gw;
    } else {
        int r = gw - BB*CC;
        if (r >= BB*QQ) return;
        row = questions + (size_t)r * DD; w = sim_w + DD;   out = g_qq + r;
    }
    float s = 0.f;
    #pragma unroll 4
    for (int d = lane; d < DD; d += 32) s += row[d] * w[d];
    #pragma unroll
    for (int o = 16; o > 0; o >>= 1) s += __shfl_xor_sync(0xffffffffu, s, o);
    if (lane == 0) *out = s;
}

// ---------------------------------------------------------------------------
// Kernel 1: sim tile + softmax + u_tilde
// ---------------------------------------------------------------------------
__global__ __launch_bounds__(256) void k_sim_u(
    const float* __restrict__ questions,
    const float* __restrict__ contexts,
    const float* __restrict__ sim_w) {
    __shared__ float sh[4224 + 4352];
    int b  = blockIdx.x >> 3;
    int ct = blockIdx.x & 7;
    int tid = threadIdx.x;
    int tx = tid & 15, ty = tid >> 4;

    const float* wp  = sim_w + 2*DD;
    const float* ctx = contexts + ((size_t)b*CC + ct*64) * DD;
    const float* qs  = questions + (size_t)b*QQ*DD;

    float acc[4][4];
    #pragma unroll
    for (int i = 0; i < 4; i++)
        #pragma unroll
        for (int j = 0; j < 4; j++) acc[i][j] = 0.f;

    float* s_a = sh;
    float* s_b = sh + 2048;

    for (int k0 = 0; k0 < DD; k0 += 32) {
        #pragma unroll
        for (int i = 0; i < 2; i++) {
            int li  = tid*2 + i;
            int row = li >> 3;
            int kq  = li & 7;
            float4 av = *(const float4*)(ctx + (size_t)row*DD + k0 + kq*4);
            float4 wv = *(const float4*)(wp + k0 + kq*4);
            s_a[(kq*4+0)*64 + row] = av.x * wv.x;
            s_a[(kq*4+1)*64 + row] = av.y * wv.y;
            s_a[(kq*4+2)*64 + row] = av.z * wv.z;
            s_a[(kq*4+3)*64 + row] = av.w * wv.w;
            float4 qv = *(const float4*)(qs + (size_t)row*DD + k0 + kq*4);
            s_b[(kq*4+0)*64 + row] = qv.x;
            s_b[(kq*4+1)*64 + row] = qv.y;
            s_b[(kq*4+2)*64 + row] = qv.z;
            s_b[(kq*4+3)*64 + row] = qv.w;
        }
        __syncthreads();
        #pragma unroll
        for (int k = 0; k < 32; k++) {
            float4 av = *(float4*)&s_a[k*64 + ty*4];
            float4 bv = *(float4*)&s_b[k*64 + tx*4];
            float a4[4] = {av.x, av.y, av.z, av.w};
            float b4[4] = {bv.x, bv.y, bv.z, bv.w};
            #pragma unroll
            for (int i = 0; i < 4; i++)
                #pragma unroll
                for (int j = 0; j < 4; j++) acc[i][j] += a4[i] * b4[j];
        }
        __syncthreads();
    }

    float* s_sim = sh;
    #pragma unroll
    for (int i = 0; i < 4; i++) {
        float cqv = g_cq[b*CC + ct*64 + ty*4 + i];
        #pragma unroll
        for (int j = 0; j < 4; j++) {
            float qqv = g_qq[b*QQ + tx*4 + j];
            s_sim[(ty*4+i)*66 + tx*4 + j] = acc[i][j] + cqv + qqv;
        }
    }
    __syncthreads();

    int wid = tid >> 5, lane = tid & 31;
    #pragma unroll
    for (int rr = 0; rr < 8; rr++) {
        int r = wid*8 + rr;
        float v0 = s_sim[r*66 + lane];
        float v1 = s_sim[r*66 + 32 + lane];
        float mx = fmaxf(v0, v1);
        #pragma unroll
        for (int o = 16; o > 0; o >>= 1) mx = fmaxf(mx, __shfl_xor_sync(0xffffffffu, mx, o));
        float e0 = __expf(v0 - mx), e1 = __expf(v1 - mx);
        float sm = e0 + e1;
        #pragma unroll
        for (int o = 16; o > 0; o >>= 1) sm += __shfl_xor_sync(0xffffffffu, sm, o);
        float inv = 1.f / sm;
        s_sim[r*66 + lane]      = e0 * inv;
        s_sim[r*66 + 32 + lane] = e1 * inv;
        if (lane == 0) g_m[b*CC + ct*64 + r] = mx;
    }
    __syncthreads();

    float* s_q2 = sh + 4224;
    for (int d0 = 0; d0 < DD; d0 += 64) {
        #pragma unroll
        for (int i = 0; i < 4; i++) {
            int li  = tid + i*256;
            int row = li >> 4;
            int dq  = li & 15;
            float4 qv = *(const float4*)(qs + (size_t)row*DD + d0 + dq*4);
            *(float4*)&s_q2[row*68 + dq*4] = qv;
        }
        __syncthreads();
        float a2[4][4];
        #pragma unroll
        for (int i = 0; i < 4; i++)
            #pragma unroll
            for (int j = 0; j < 4; j++) a2[i][j] = 0.f;
        #pragma unroll 8
        for (int k = 0; k < 64; k++) {
            float p0 = s_sim[(ty*4+0)*66 + k];
            float p1 = s_sim[(ty*4+1)*66 + k];
            float p2 = s_sim[(ty*4+2)*66 + k];
            float p3 = s_sim[(ty*4+3)*66 + k];
            float4 qv = *(float4*)&s_q2[k*68 + tx*4];
            float q4[4] = {qv.x, qv.y, qv.z, qv.w};
            #pragma unroll
            for (int j = 0; j < 4; j++) {
                a2[0][j] += p0 * q4[j];
                a2[1][j] += p1 * q4[j];
                a2[2][j] += p2 * q4[j];
                a2[3][j] += p3 * q4[j];
            }
        }
        #pragma unroll
        for (int i = 0; i < 4; i++) {
            float4 w4 = make_float4(a2[i][0], a2[i][1], a2[i][2], a2[i][3]);
            *(float4*)&g_u[((size_t)b*CC + ct*64 + ty*4 + i)*DD + d0 + tx*4] = w4;
        }
        __syncthreads();
    }
}

// ---------------------------------------------------------------------------
// Kernel 2a: attn softmax over C
// ---------------------------------------------------------------------------
__global__ void k_attn() {
    __shared__ float red[256];
    int b = blockIdx.x, tid = threadIdx.x;
    float v0 = g_m[b*CC + tid], v1 = g_m[b*CC + 256 + tid];
    float mx = fmaxf(v0, v1);
    red[tid] = mx; __syncthreads();
    for (int s = 128; s > 0; s >>= 1) {
        if (tid < s) red[tid] = fmaxf(red[tid], red[tid + s]);
        __syncthreads();
    }
    mx = red[0]; __syncthreads();
    float e0 = __expf(v0 - mx), e1 = __expf(v1 - mx);
    red[tid] = e0 + e1; __syncthreads();
    for (int s = 128; s > 0; s >>= 1) {
        if (tid < s) red[tid] += red[tid + s];
        __syncthreads();
    }
    float inv = 1.f / red[0];
    g_attn[b*CC + tid]       = e0 * inv;
    g_attn[b*CC + 256 + tid] = e1 * inv;
}

// ---------------------------------------------------------------------------
// Kernel 2b: h_tilde
// ---------------------------------------------------------------------------
__global__ void k_h(const float* __restrict__ contexts) {
    __shared__ float sa[CC];
    int b = blockIdx.x >> 2;
    int d = (blockIdx.x & 3) * 128 + threadIdx.x;
    for (int i = threadIdx.x; i < CC; i += 128) sa[i] = g_attn[b*CC + i];
    __syncthreads();
    const float* ctx = contexts + (size_t)b*CC*DD;
    float acc = 0.f;
    #pragma unroll 8
    for (int c = 0; c < CC; c++) acc += sa[c] * ctx[(size_t)c*DD + d];
    g_h[b*DD + d] = acc;
}

// ---------------------------------------------------------------------------
// Kernel 3: megamerge -> bf16 hi/lo split (A operand of the big GEMM)
// ---------------------------------------------------------------------------
__global__ void k_mm(const float* __restrict__ contexts) {
    size_t i4 = (size_t)blockIdx.x * 256 + threadIdx.x;   // MTOT*D4/4
    int m   = (int)(i4 >> 9);
    int k4  = (int)(i4 & 511);
    int seg = k4 >> 7;
    int off = (k4 & 127) * 4;
    int b   = m >> 9;
    float4 cv = *(const float4*)(contexts + (size_t)m*DD + off);
    float4 r;
    if (seg == 0) {
        r = cv;
    } else if (seg == 3) {
        float4 hv = *(const float4*)(g_h + (size_t)b*DD + off);
        r = make_float4(cv.x*hv.x, cv.y*hv.y, cv.z*hv.z, cv.w*hv.w);
    } else {
        float4 uv = *(const float4*)(g_u + (size_t)m*DD + off);
        r = (seg == 1) ? uv
                       : make_float4(uv.x*cv.x, uv.y*cv.y, uv.z*cv.z, uv.w*cv.w);
    }
    uint2 h4, l4;
    split2(r.x, r.y, h4.x, l4.x);
    split2(r.z, r.w, h4.y, l4.y);
    ((uint2*)g_Ahi)[i4] = h4;
    ((uint2*)g_Alo)[i4] = l4;
}

// ---------------------------------------------------------------------------
// Kernel 3b: qac_w -> bf16 hi/lo split (B operand)
// ---------------------------------------------------------------------------
__global__ void k_wsplit(const float* __restrict__ w) {
    size_t i4 = (size_t)blockIdx.x * 256 + threadIdx.x;   // D4*D4/4
    float4 v = ((const float4*)w)[i4];
    uint2 h4, l4;
    split2(v.x, v.y, h4.x, l4.x);
    split2(v.z, v.w, h4.y, l4.y);
    ((uint2*)g_Bhi)[i4] = h4;
    ((uint2*)g_Blo)[i4] = l4;
}

// ---------------------------------------------------------------------------
// Kernel 4: mma.sync bf16 GEMM (3-term split, shared operand loads)
//   out = Ahi*Bhi^T + Alo*Bhi^T + Ahi*Blo^T + bias
// Per K-chunk (64), load 4 tiles {Ahi, Alo, Bhi, Blo} ONCE, run 3 MMA terms.
// 32 iters, 3-stage cp.async pipeline (72 KB/stage).
// CTA tile 128x128, 8 warps (2x4), warp tile 64x32, mma.m16n8k16.
// ---------------------------------------------------------------------------
#define ROWB 144
#define ASTG (128*ROWB)          // 18432 B per tile
#define STG3B (4*ASTG)           // 73728 B per stage (Ahi|Alo|Bhi|Blo)
#define GSMEM2 (3*STG3B)         // 221184 B

__global__ __launch_bounds__(256) void k_gemm_mma(
    const float* __restrict__ bias, float* __restrict__ out) {
    extern __shared__ char smem[];
    uint32_t su = smem_u32(smem);
    int tid  = threadIdx.x;
    int lane = tid & 31;
    int w    = tid >> 5;
    int wm   = w >> 2;          // 0..1
    int wn   = w & 3;           // 0..3
    int n0 = blockIdx.x * 128;
    int m0 = blockIdx.y * 128;

    float acc[4][4][4];
    #pragma unroll
    for (int i = 0; i < 4; i++)
        #pragma unroll
        for (int p = 0; p < 4; p++)
            #pragma unroll
            for (int e = 0; e < 4; e++) acc[i][p][e] = 0.f;

    int lrow = tid >> 3;        // 0..31
    int lchk = tid & 7;         // 16B chunk within 128B row

    // stage loader: it = K-chunk index 0..31
    auto load_stage = [&](int it, int s) {
        int kbase = it * 64;
        uint32_t sb = su + s*STG3B;
        #pragma unroll
        for (int i = 0; i < 4; i++) {
            int row = lrow + i*32;
            size_t aoff = (size_t)(m0 + row)*D4 + kbase + lchk*8;
            size_t boff = (size_t)(n0 + row)*D4 + kbase + lchk*8;
            uint32_t d = sb + row*ROWB + lchk*16;
            CP16(d,          (const void*)(g_Ahi + aoff));
            CP16(d +   ASTG, (const void*)(g_Alo + aoff));
            CP16(d + 2*ASTG, (const void*)(g_Bhi + boff));
            CP16(d + 3*ASTG, (const void*)(g_Blo + boff));
        }
        asm volatile("cp.async.commit_group;" ::: "memory");
    };

    load_stage(0, 0);
    load_stage(1, 1);

    // ldmatrix lane addressing (within a 16x16 tile)
    int lr16 = (lane & 7) + ((lane >> 3) & 1) * 8;   // row 0..15
    int lc16 = lane >> 4;                             // chunk 0/1

    for (int it = 0; it < 32; it++) {
        int s = it % 3;
        if (it < 31) {
            asm volatile("cp.async.wait_group %0;" :: "n"(1) : "memory");
        } else {
            asm volatile("cp.async.wait_group %0;" :: "n"(0) : "memory");
        }
        __syncthreads();

        uint32_t base = su + s*STG3B;
        uint32_t aW = base + (wm*64 + lr16)*ROWB + lc16*16;
        uint32_t bW = base + 2*ASTG + (wn*32 + lr16)*ROWB + lc16*16;

        #pragma unroll
        for (int j = 0; j < 4; j++) {
            uint32_t afh[4][4], afl[4][4];
            #pragma unroll
            for (int i = 0; i < 4; i++)
                LDSM4(afh[i], aW + i*16*ROWB + j*32);
            #pragma unroll
            for (int i = 0; i < 4; i++)
                LDSM4(afl[i], aW + ASTG + i*16*ROWB + j*32);
            uint32_t bfh[2][4], bfl[2][4];
            #pragma unroll
            for (int h = 0; h < 2; h++)
                LDSM4(bfh[h], bW + h*16*ROWB + j*32);
            #pragma unroll
            for (int h = 0; h < 2; h++)
                LDSM4(bfl[h], bW + ASTG + h*16*ROWB + j*32);
            #pragma unroll
            for (int i = 0; i < 4; i++)
                #pragma unroll
                for (int p = 0; p < 4; p++) {
                    uint32_t bh0 = bfh[p>>1][p&1], bh1 = bfh[p>>1][(p&1)+2];
                    uint32_t bl0 = bfl[p>>1][p&1], bl1 = bfl[p>>1][(p&1)+2];
                    mma16816(acc[i][p], afh[i], bh0, bh1);
                    mma16816(acc[i][p], afl[i], bh0, bh1);
                    mma16816(acc[i][p], afh[i], bl0, bl1);
                }
        }

        // issue next-next stage load (into buffer (it+2)%3, last read at it-1,
        // protected by the __syncthreads() above)
        if (it + 2 < 32) load_stage(it + 2, (it + 2) % 3);
    }

    // Epilogue: c0,c1 -> (row g, col 2t,2t+1); c2,c3 -> row g+8
    int g = lane >> 2, t = lane & 3;
    #pragma unroll
    for (int i = 0; i < 4; i++) {
        int row = m0 + wm*64 + i*16 + g;
        #pragma unroll
        for (int p = 0; p < 4; p++) {
            int col = n0 + wn*32 + p*8 + 2*t;
            float b0 = bias[col], b1 = bias[col + 1];
            float2 v0 = make_float2(acc[i][p][0] + b0, acc[i][p][1] + b1);
            float2 v1 = make_float2(acc[i][p][2] + b0, acc[i][p][3] + b1);
            *(float2*)(out + (size_t)row*D4 + col)       = v0;
            *(float2*)(out + (size_t)(row + 8)*D4 + col) = v1;
        }
    }
}

// ---------------------------------------------------------------------------
extern "C" void kernel_launch(void* const* d_in, const int* in_sizes, int n_in,
                              void* d_out, int out_size) {
    const float* questions = (const float*)d_in[0];
    const float* contexts  = (const float*)d_in[1];
    const float* sim_w     = (const float*)d_in[2];
    const float* qac_w     = (const float*)d_in[3];
    const float* qac_b     = (const float*)d_in[4];
    float* out = (float*)d_out;

    cudaFuncSetAttribute(k_gemm_mma, cudaFuncAttributeMaxDynamicSharedMemorySize, GSMEM2);

    k_wsplit<<<4096, 256>>>(qac_w);
    k_rowdots<<<1152, 256>>>(questions, contexts, sim_w);
    k_sim_u<<<128, 256>>>(questions, contexts, sim_w);
    k_attn<<<16, 256>>>();
    k_h<<<64, 128>>>(contexts);
    k_mm<<<16384, 256>>>(contexts);
    k_gemm_mma<<<dim3(16, 64), 256, GSMEM2>>>(qac_b, out);
}

// round 5
// speedup vs baseline: 3.3711x; 1.3425x over previous
#include <cuda_runtime.h>
#include <cuda_fp16.h>
#include <math.h>
#include <stdint.h>

// Problem constants
#define BB 16
#define QQ 64
#define CC 512
#define DD 512
#define D4 2048
#define MTOT (BB*CC)   // 8192

// Scratch (device globals: allocation-free rule)
__device__ float g_cq[BB*CC];
__device__ float g_qq[BB*QQ];
__device__ float g_m[BB*CC];
__device__ float g_attn[BB*CC];
__device__ float g_h[BB*DD];
__device__ float g_u[(size_t)BB*CC*DD];                      // 16.8 MB
__device__ __align__(16) __half g_Ahi[(size_t)MTOT*D4];      // 32 MB
__device__ __align__(16) __half g_Alo[(size_t)MTOT*D4];      // 32 MB
__device__ __align__(16) __half g_Bhi[(size_t)D4*D4];        // 8 MB

__device__ __forceinline__ uint32_t smem_u32(const void* p) {
    uint32_t a;
    asm("{ .reg .u64 t; cvta.to.shared.u64 t, %1; cvt.u32.u64 %0, t; }"
        : "=r"(a) : "l"(p));
    return a;
}

#define LDSM4(r, addr) \
    asm volatile("ldmatrix.sync.aligned.m8n8.x4.shared.b16 {%0,%1,%2,%3}, [%4];" \
        : "=r"((r)[0]), "=r"((r)[1]), "=r"((r)[2]), "=r"((r)[3]) : "r"(addr))

#define CP16(dst, src) \
    asm volatile("cp.async.cg.shared.global [%0], [%1], 16;" \
        :: "r"(dst), "l"(src) : "memory")

__device__ __forceinline__ void mma16816(float* d, const uint32_t* a,
                                         uint32_t b0, uint32_t b1) {
    asm volatile(
        "mma.sync.aligned.m16n8k16.row.col.f32.f16.f16.f32 "
        "{%0,%1,%2,%3}, {%4,%5,%6,%7}, {%8,%9}, {%0,%1,%2,%3};"
        : "+f"(d[0]), "+f"(d[1]), "+f"(d[2]), "+f"(d[3])
        : "r"(a[0]), "r"(a[1]), "r"(a[2]), "r"(a[3]), "r"(b0), "r"(b1));
}

// fp16 two-term split: packs (x,y) hi and lo pairs
__device__ __forceinline__ void split2h(float x, float y, uint32_t& hi, uint32_t& lo) {
    __half hx = __float2half_rn(x);
    __half hy = __float2half_rn(y);
    __half lx = __float2half_rn(x - __half2float(hx));
    __half ly = __float2half_rn(y - __half2float(hy));
    hi = ((uint32_t)__half_as_ushort(hy) << 16) | (uint32_t)__half_as_ushort(hx);
    lo = ((uint32_t)__half_as_ushort(ly) << 16) | (uint32_t)__half_as_ushort(lx);
}

// ---------------------------------------------------------------------------
// Kernel 0: cq[b,c] = ctx_row . w_c ; qq[b,q] = q_row . w_q   (warp per row)
// ---------------------------------------------------------------------------
__global__ void k_rowdots(const float* __restrict__ questions,
                          const float* __restrict__ contexts,
                          const float* __restrict__ sim_w) {
    int gw   = (blockIdx.x * blockDim.x + threadIdx.x) >> 5;
    int lane = threadIdx.x & 31;
    const float* row;
    const float* w;
    float* out;
    if (gw < BB*CC) {
        row = contexts + (size_t)gw * DD; w = sim_w;        out = g_cq + gw;
    } else {
        int r = gw - BB*CC;
        if (r >= BB*QQ) return;
        row = questions + (size_t)r * DD; w = sim_w + DD;   out = g_qq + r;
    }
    float s = 0.f;
    #pragma unroll 4
    for (int d = lane; d < DD; d += 32) s += row[d] * w[d];
    #pragma unroll
    for (int o = 16; o > 0; o >>= 1) s += __shfl_xor_sync(0xffffffffu, s, o);
    if (lane == 0) *out = s;
}

// ---------------------------------------------------------------------------
// Kernel 1: sim tile + softmax + u_tilde
// ---------------------------------------------------------------------------
__global__ __launch_bounds__(256) void k_sim_u(
    const float* __restrict__ questions,
    const float* __restrict__ contexts,
    const float* __restrict__ sim_w) {
    __shared__ float sh[4224 + 4352];
    int b  = blockIdx.x >> 3;
    int ct = blockIdx.x & 7;
    int tid = threadIdx.x;
    int tx = tid & 15, ty = tid >> 4;

    const float* wp  = sim_w + 2*DD;
    const float* ctx = contexts + ((size_t)b*CC + ct*64) * DD;
    const float* qs  = questions + (size_t)b*QQ*DD;

    float acc[4][4];
    #pragma unroll
    for (int i = 0; i < 4; i++)
        #pragma unroll
        for (int j = 0; j < 4; j++) acc[i][j] = 0.f;

    float* s_a = sh;
    float* s_b = sh + 2048;

    for (int k0 = 0; k0 < DD; k0 += 32) {
        #pragma unroll
        for (int i = 0; i < 2; i++) {
            int li  = tid*2 + i;
            int row = li >> 3;
            int kq  = li & 7;
            float4 av = *(const float4*)(ctx + (size_t)row*DD + k0 + kq*4);
            float4 wv = *(const float4*)(wp + k0 + kq*4);
            s_a[(kq*4+0)*64 + row] = av.x * wv.x;
            s_a[(kq*4+1)*64 + row] = av.y * wv.y;
            s_a[(kq*4+2)*64 + row] = av.z * wv.z;
            s_a[(kq*4+3)*64 + row] = av.w * wv.w;
            float4 qv = *(const float4*)(qs + (size_t)row*DD + k0 + kq*4);
            s_b[(kq*4+0)*64 + row] = qv.x;
            s_b[(kq*4+1)*64 + row] = qv.y;
            s_b[(kq*4+2)*64 + row] = qv.z;
            s_b[(kq*4+3)*64 + row] = qv.w;
        }
        __syncthreads();
        #pragma unroll
        for (int k = 0; k < 32; k++) {
            float4 av = *(float4*)&s_a[k*64 + ty*4];
            float4 bv = *(float4*)&s_b[k*64 + tx*4];
            float a4[4] = {av.x, av.y, av.z, av.w};
            float b4[4] = {bv.x, bv.y, bv.z, bv.w};
            #pragma unroll
            for (int i = 0; i < 4; i++)
                #pragma unroll
                for (int j = 0; j < 4; j++) acc[i][j] += a4[i] * b4[j];
        }
        __syncthreads();
    }

    float* s_sim = sh;
    #pragma unroll
    for (int i = 0; i < 4; i++) {
        float cqv = g_cq[b*CC + ct*64 + ty*4 + i];
        #pragma unroll
        for (int j = 0; j < 4; j++) {
            float qqv = g_qq[b*QQ + tx*4 + j];
            s_sim[(ty*4+i)*66 + tx*4 + j] = acc[i][j] + cqv + qqv;
        }
    }
    __syncthreads();

    int wid = tid >> 5, lane = tid & 31;
    #pragma unroll
    for (int rr = 0; rr < 8; rr++) {
        int r = wid*8 + rr;
        float v0 = s_sim[r*66 + lane];
        float v1 = s_sim[r*66 + 32 + lane];
        float mx = fmaxf(v0, v1);
        #pragma unroll
        for (int o = 16; o > 0; o >>= 1) mx = fmaxf(mx, __shfl_xor_sync(0xffffffffu, mx, o));
        float e0 = __expf(v0 - mx), e1 = __expf(v1 - mx);
        float sm = e0 + e1;
        #pragma unroll
        for (int o = 16; o > 0; o >>= 1) sm += __shfl_xor_sync(0xffffffffu, sm, o);
        float inv = 1.f / sm;
        s_sim[r*66 + lane]      = e0 * inv;
        s_sim[r*66 + 32 + lane] = e1 * inv;
        if (lane == 0) g_m[b*CC + ct*64 + r] = mx;
    }
    __syncthreads();

    float* s_q2 = sh + 4224;
    for (int d0 = 0; d0 < DD; d0 += 64) {
        #pragma unroll
        for (int i = 0; i < 4; i++) {
            int li  = tid + i*256;
            int row = li >> 4;
            int dq  = li & 15;
            float4 qv = *(const float4*)(qs + (size_t)row*DD + d0 + dq*4);
            *(float4*)&s_q2[row*68 + dq*4] = qv;
        }
        __syncthreads();
        float a2[4][4];
        #pragma unroll
        for (int i = 0; i < 4; i++)
            #pragma unroll
            for (int j = 0; j < 4; j++) a2[i][j] = 0.f;
        #pragma unroll 8
        for (int k = 0; k < 64; k++) {
            float p0 = s_sim[(ty*4+0)*66 + k];
            float p1 = s_sim[(ty*4+1)*66 + k];
            float p2 = s_sim[(ty*4+2)*66 + k];
            float p3 = s_sim[(ty*4+3)*66 + k];
            float4 qv = *(float4*)&s_q2[k*68 + tx*4];
            float q4[4] = {qv.x, qv.y, qv.z, qv.w};
            #pragma unroll
            for (int j = 0; j < 4; j++) {
                a2[0][j] += p0 * q4[j];
                a2[1][j] += p1 * q4[j];
                a2[2][j] += p2 * q4[j];
                a2[3][j] += p3 * q4[j];
            }
        }
        #pragma unroll
        for (int i = 0; i < 4; i++) {
            float4 w4 = make_float4(a2[i][0], a2[i][1], a2[i][2], a2[i][3]);
            *(float4*)&g_u[((size_t)b*CC + ct*64 + ty*4 + i)*DD + d0 + tx*4] = w4;
        }
        __syncthreads();
    }
}

// ---------------------------------------------------------------------------
// Kernel 2a: attn softmax over C
// ---------------------------------------------------------------------------
__global__ void k_attn() {
    __shared__ float red[256];
    int b = blockIdx.x, tid = threadIdx.x;
    float v0 = g_m[b*CC + tid], v1 = g_m[b*CC + 256 + tid];
    float mx = fmaxf(v0, v1);
    red[tid] = mx; __syncthreads();
    for (int s = 128; s > 0; s >>= 1) {
        if (tid < s) red[tid] = fmaxf(red[tid], red[tid + s]);
        __syncthreads();
    }
    mx = red[0]; __syncthreads();
    float e0 = __expf(v0 - mx), e1 = __expf(v1 - mx);
    red[tid] = e0 + e1; __syncthreads();
    for (int s = 128; s > 0; s >>= 1) {
        if (tid < s) red[tid] += red[tid + s];
        __syncthreads();
    }
    float inv = 1.f / red[0];
    g_attn[b*CC + tid]       = e0 * inv;
    g_attn[b*CC + 256 + tid] = e1 * inv;
}

// ---------------------------------------------------------------------------
// Kernel 2b: h_tilde — 128 blocks x 128 thr, 2-way c-split per thread
// ---------------------------------------------------------------------------
__global__ void k_h(const float* __restrict__ contexts) {
    __shared__ float sa[CC];
    __shared__ float part[128];
    int b  = blockIdx.x >> 3;
    int dc = blockIdx.x & 7;
    int tid = threadIdx.x;
    int d = dc*64 + (tid & 63);
    int h = tid >> 6;                 // 0/1 -> c half
    for (int i = tid; i < CC; i += 128) sa[i] = g_attn[b*CC + i];
    __syncthreads();
    const float* ctx = contexts + (size_t)b*CC*DD + (size_t)h*256*DD;
    float acc = 0.f;
    #pragma unroll 8
    for (int c = 0; c < 256; c++) acc += sa[h*256 + c] * ctx[(size_t)c*DD + d];
    part[tid] = acc;
    __syncthreads();
    if (h == 0) g_h[b*DD + d] = part[tid] + part[tid + 64];
}

// ---------------------------------------------------------------------------
// Kernel 3: megamerge -> fp16 hi/lo split (A operand of the big GEMM)
// ---------------------------------------------------------------------------
__global__ void k_mm(const float* __restrict__ contexts) {
    size_t i4 = (size_t)blockIdx.x * 256 + threadIdx.x;   // MTOT*D4/4
    int m   = (int)(i4 >> 9);
    int k4  = (int)(i4 & 511);
    int seg = k4 >> 7;
    int off = (k4 & 127) * 4;
    int b   = m >> 9;
    float4 cv = *(const float4*)(contexts + (size_t)m*DD + off);
    float4 r;
    if (seg == 0) {
        r = cv;
    } else if (seg == 3) {
        float4 hv = *(const float4*)(g_h + (size_t)b*DD + off);
        r = make_float4(cv.x*hv.x, cv.y*hv.y, cv.z*hv.z, cv.w*hv.w);
    } else {
        float4 uv = *(const float4*)(g_u + (size_t)m*DD + off);
        r = (seg == 1) ? uv
                       : make_float4(uv.x*cv.x, uv.y*cv.y, uv.z*cv.z, uv.w*cv.w);
    }
    uint2 h4, l4;
    split2h(r.x, r.y, h4.x, l4.x);
    split2h(r.z, r.w, h4.y, l4.y);
    ((uint2*)g_Ahi)[i4] = h4;
    ((uint2*)g_Alo)[i4] = l4;
}

// ---------------------------------------------------------------------------
// Kernel 3b: qac_w -> fp16 hi (B operand, single term)
// ---------------------------------------------------------------------------
__global__ void k_wsplit(const float* __restrict__ w) {
    size_t i4 = (size_t)blockIdx.x * 256 + threadIdx.x;   // D4*D4/4
    float4 v = ((const float4*)w)[i4];
    uint2 h4;
    __half hx = __float2half_rn(v.x), hy = __float2half_rn(v.y);
    __half hz = __float2half_rn(v.z), hw = __float2half_rn(v.w);
    h4.x = ((uint32_t)__half_as_ushort(hy) << 16) | (uint32_t)__half_as_ushort(hx);
    h4.y = ((uint32_t)__half_as_ushort(hw) << 16) | (uint32_t)__half_as_ushort(hz);
    ((uint2*)g_Bhi)[i4] = h4;
}

// ---------------------------------------------------------------------------
// Kernel 4: mma.sync fp16 GEMM (2-term split, K_eff = 4096)
//   out = Ahi*Bhi^T + Alo*Bhi^T + bias   (error = A*Blo ~ 1.5e-4 rel)
// Per K-chunk (64): load 3 tiles {Ahi, Alo, Bhi} once; 2 MMA terms.
// 32 iters, 3-stage cp.async pipeline (54 KB/stage).
// CTA tile 128x128, 8 warps (2x4), warp tile 64x32, mma.m16n8k16.
// ---------------------------------------------------------------------------
#define ROWB 144
#define ASTG (128*ROWB)          // 18432 B per tile
#define STG3B (3*ASTG)           // 55296 B per stage (Ahi|Alo|Bhi)
#define GSMEM2 (3*STG3B)         // 165888 B

__global__ __launch_bounds__(256) void k_gemm_mma(
    const float* __restrict__ bias, float* __restrict__ out) {
    extern __shared__ char smem[];
    uint32_t su = smem_u32(smem);
    int tid  = threadIdx.x;
    int lane = tid & 31;
    int w    = tid >> 5;
    int wm   = w >> 2;          // 0..1
    int wn   = w & 3;           // 0..3
    int n0 = blockIdx.x * 128;
    int m0 = blockIdx.y * 128;

    float acc[4][4][4];
    #pragma unroll
    for (int i = 0; i < 4; i++)
        #pragma unroll
        for (int p = 0; p < 4; p++)
            #pragma unroll
            for (int e = 0; e < 4; e++) acc[i][p][e] = 0.f;

    int lrow = tid >> 3;        // 0..31
    int lchk = tid & 7;         // 16B chunk within 128B row

    auto load_stage = [&](int it, int s) {
        int kbase = it * 64;
        uint32_t sb = su + s*STG3B;
        #pragma unroll
        for (int i = 0; i < 4; i++) {
            int row = lrow + i*32;
            size_t aoff = (size_t)(m0 + row)*D4 + kbase + lchk*8;
            size_t boff = (size_t)(n0 + row)*D4 + kbase + lchk*8;
            uint32_t d = sb + row*ROWB + lchk*16;
            CP16(d,          (const void*)(g_Ahi + aoff));
            CP16(d +   ASTG, (const void*)(g_Alo + aoff));
            CP16(d + 2*ASTG, (const void*)(g_Bhi + boff));
        }
        asm volatile("cp.async.commit_group;" ::: "memory");
    };

    load_stage(0, 0);
    load_stage(1, 1);

    int lr16 = (lane & 7) + ((lane >> 3) & 1) * 8;   // row 0..15
    int lc16 = lane >> 4;                             // chunk 0/1

    for (int it = 0; it < 32; it++) {
        int s = it % 3;
        if (it < 31) {
            asm volatile("cp.async.wait_group %0;" :: "n"(1) : "memory");
        } else {
            asm volatile("cp.async.wait_group %0;" :: "n"(0) : "memory");
        }
        __syncthreads();

        uint32_t base = su + s*STG3B;
        uint32_t aW = base + (wm*64 + lr16)*ROWB + lc16*16;
        uint32_t bW = base + 2*ASTG + (wn*32 + lr16)*ROWB + lc16*16;

        #pragma unroll
        for (int j = 0; j < 4; j++) {
            uint32_t afh[4][4], afl[4][4];
            #pragma unroll
            for (int i = 0; i < 4; i++)
                LDSM4(afh[i], aW + i*16*ROWB + j*32);
            #pragma unroll
            for (int i = 0; i < 4; i++)
                LDSM4(afl[i], aW + ASTG + i*16*ROWB + j*32);
            uint32_t bfh[2][4];
            #pragma unroll
            for (int h = 0; h < 2; h++)
                LDSM4(bfh[h], bW + h*16*ROWB + j*32);
            #pragma unroll
            for (int i = 0; i < 4; i++)
                #pragma unroll
                for (int p = 0; p < 4; p++) {
                    uint32_t bh0 = bfh[p>>1][p&1], bh1 = bfh[p>>1][(p&1)+2];
                    mma16816(acc[i][p], afh[i], bh0, bh1);
                    mma16816(acc[i][p], afl[i], bh0, bh1);
                }
        }

        if (it + 2 < 32) load_stage(it + 2, (it + 2) % 3);
    }

    // Epilogue
    int g = lane >> 2, t = lane & 3;
    #pragma unroll
    for (int i = 0; i < 4; i++) {
        int row = m0 + wm*64 + i*16 + g;
        #pragma unroll
        for (int p = 0; p < 4; p++) {
            int col = n0 + wn*32 + p*8 + 2*t;
            float b0 = bias[col], b1 = bias[col + 1];
            float2 v0 = make_float2(acc[i][p][0] + b0, acc[i][p][1] + b1);
            float2 v1 = make_float2(acc[i][p][2] + b0, acc[i][p][3] + b1);
            *(float2*)(out + (size_t)row*D4 + col)       = v0;
            *(float2*)(out + (size_t)(row + 8)*D4 + col) = v1;
        }
    }
}

// ---------------------------------------------------------------------------
extern "C" void kernel_launch(void* const* d_in, const int* in_sizes, int n_in,
                              void* d_out, int out_size) {
    const float* questions = (const float*)d_in[0];
    const float* contexts  = (const float*)d_in[1];
    const float* sim_w     = (const float*)d_in[2];
    const float* qac_w     = (const float*)d_in[3];
    const float* qac_b     = (const float*)d_in[4];
    float* out = (float*)d_out;

    cudaFuncSetAttribute(k_gemm_mma, cudaFuncAttributeMaxDynamicSharedMemorySize, GSMEM2);

    k_wsplit<<<4096, 256>>>(qac_w);
    k_rowdots<<<1152, 256>>>(questions, contexts, sim_w);
    k_sim_u<<<128, 256>>>(questions, contexts, sim_w);
    k_attn<<<16, 256>>>();
    k_h<<<128, 128>>>(contexts);
    k_mm<<<16384, 256>>>(contexts);
    k_gemm_mma<<<dim3(16, 64), 256, GSMEM2>>>(qac_b, out);
}